// round 14
// baseline (speedup 1.0000x reference)
#include <cuda_runtime.h>
#include <cuda_fp16.h>
#include <math.h>

#define CC    10
#define CH    5        // capsules per chunk
#define NN    1152
#define DIN   8
#define DOUT  16
#define BB    256

typedef unsigned long long ull;

// Double-buffered fp16 priors scratch: [buf][c_local][b][n][o], 2 x 47.2 MB.
__device__ __half g_pri[2][(size_t)CH * BB * NN * DOUT];

// ---- packed f32x2 helpers (Blackwell FFMA2 — PTX-only) ----
__device__ __forceinline__ ull pack2(float lo, float hi) {
    ull r; asm("mov.b64 %0, {%1, %2};" : "=l"(r) : "f"(lo), "f"(hi)); return r;
}
__device__ __forceinline__ float2 unpack2(ull v) {
    float2 f; asm("mov.b64 {%0, %1}, %2;" : "=f"(f.x), "=f"(f.y) : "l"(v)); return f;
}
__device__ __forceinline__ ull fma2(ull a, ull b, ull c) {
    ull d; asm("fma.rn.f32x2 %0, %1, %2, %3;" : "=l"(d) : "l"(a), "l"(b), "l"(c)); return d;
}
__device__ __forceinline__ ull add2(ull a, ull b) {
    ull d; asm("add.rn.f32x2 %0, %1, %2;" : "=l"(d) : "l"(a), "l"(b)); return d;
}
__device__ __forceinline__ ull h2_to_f32x2(unsigned int h2) {
    ull d;
    asm("{\n\t"
        ".reg .f16 h0, h1;\n\t"
        ".reg .f32 f0, f1;\n\t"
        "mov.b32 {h0, h1}, %1;\n\t"
        "cvt.f32.f16 f0, h0;\n\t"
        "cvt.f32.f16 f1, h1;\n\t"
        "mov.b64 %0, {f0, f1};\n\t"
        "}" : "=l"(d) : "r"(h2));
    return d;
}
__device__ __forceinline__ unsigned int f32x2_to_h2(ull v) {
    unsigned int r;
    asm("{\n\t"
        ".reg .f32 lo, hi;\n\t"
        "mov.b64 {lo, hi}, %1;\n\t"
        "cvt.rn.f16x2.f32 %0, hi, lo;\n\t"
        "}" : "=r"(r) : "l"(v));
    return r;
}

// Fused kernel: P CTAs FIRST in grid (blk < nPblk), R CTAs after.
//   P blocks: CH*9*8 = 360 when active. R blocks: CH*BB = 1280 when active.
#define PBLKS (CH * 9 * 8)     // 360
#define RBLKS (CH * BB)        // 1280
#define NW3   8
#define KPT3  9

__global__ __launch_bounds__(256, 4)
void fused_kernel(const float* __restrict__ x, const float* __restrict__ W,
                  float* __restrict__ out,
                  int c0P, int bufP, int c0R, int bufR, int nPblk) {
    __shared__ __align__(16) __half spri[NN * DOUT];   // 36864 B (R path only)
    __shared__ float red[16 * NW3];
    __shared__ float sew[NW3];
    __shared__ __align__(16) float outv[16];

    const int blk = blockIdx.x;
    const int tid = threadIdx.x;

    if (blk < nPblk) {
        // ================== PRIORS path (R11's priors_kernel, flattened) ==================
        // block p: cl = p/72, ny = (p%72)>>3 (0..8), z = p&7.
        // thread: oh = tid&1 (o-half), nn = tid>>1 (128 nodes/block).
        const int p  = blk;
        const int cl = p / 72;
        const int rr = p % 72;
        const int ny = rr >> 3;
        const int z  = rr & 7;
        const int oh = tid & 1;
        const int nn = tid >> 1;
        const int cg = c0P + cl;
        const int n  = ny * 128 + nn;
        const int b0 = z * 32;

        // Load this (n, oh) W slice ONCE: 8 i x 8 o = 64 floats -> 32 f32x2 regs.
        ull w2[32];
        {
            const float4* wr = reinterpret_cast<const float4*>(
                W + (((size_t)cg * NN + n) * DIN) * DOUT + oh * 8);
#pragma unroll
            for (int i = 0; i < 8; ++i) {
                float4 q0 = wr[i * 4 + 0];
                float4 q1 = wr[i * 4 + 1];
                w2[i * 4 + 0] = pack2(q0.x, q0.y);
                w2[i * 4 + 1] = pack2(q0.z, q0.w);
                w2[i * 4 + 2] = pack2(q1.x, q1.y);
                w2[i * 4 + 3] = pack2(q1.z, q1.w);
            }
        }

        uint4* op = reinterpret_cast<uint4*>(g_pri[bufP]);

#pragma unroll 2
        for (int bb = 0; bb < 32; ++bb) {
            const int b = b0 + bb;
            const float4* xr = reinterpret_cast<const float4*>(x + ((size_t)b * NN + n) * DIN);
            float4 v0 = xr[0], v1 = xr[1];
            float xa[8];
            xa[0]=v0.x; xa[1]=v0.y; xa[2]=v0.z; xa[3]=v0.w;
            xa[4]=v1.x; xa[5]=v1.y; xa[6]=v1.z; xa[7]=v1.w;

            ull acc[4] = {0ull, 0ull, 0ull, 0ull};
#pragma unroll
            for (int i = 0; i < 8; ++i) {
                ull xs = pack2(xa[i], xa[i]);
#pragma unroll
                for (int pq = 0; pq < 4; ++pq)
                    acc[pq] = fma2(xs, w2[i * 4 + pq], acc[pq]);
            }
            uint4 o;
            o.x = f32x2_to_h2(acc[0]);
            o.y = f32x2_to_h2(acc[1]);
            o.z = f32x2_to_h2(acc[2]);
            o.w = f32x2_to_h2(acc[3]);
            op[((size_t)(cl * BB + b) * NN + n) * 2 + oh] = o;
        }
        return;
    }

    // ================== ROUTING path (R11's routing_kernel) ==================
    const int rblk = blk - nPblk;
    const int lane = tid & 31;
    const int wid  = tid >> 5;
    const int oh   = tid & 1;     // owns o = oh*8 .. oh*8+7
    const int g    = tid >> 1;    // node group 0..127
    const int cl   = rblk >> 8;   // chunk-local capsule
    const int cg   = c0R + cl;    // global capsule (for out)
    const int b    = rblk & 255;

    // ---- load priors tile: 2304 x 16B, fully coalesced ----
    {
        const uint4* src = reinterpret_cast<const uint4*>(g_pri[bufR])
                         + (size_t)(cl * BB + b) * NN * 2;
        uint4* dst = reinterpret_cast<uint4*>(spri);
#pragma unroll
        for (int t = 0; t < 9; ++t)
            dst[tid + t * 256] = src[tid + t * 256];
    }
    __syncthreads();

    // ---- iter 0: uniform weights -> s = mean over n, squash ----
    {
        ull s2[4] = {0ull, 0ull, 0ull, 0ull};
#pragma unroll
        for (int k = 0; k < KPT3; ++k) {
            const uint4 h = *reinterpret_cast<const uint4*>(&spri[(g + 128 * k) * 16 + oh * 8]);
            s2[0] = add2(s2[0], h2_to_f32x2(h.x));
            s2[1] = add2(s2[1], h2_to_f32x2(h.y));
            s2[2] = add2(s2[2], h2_to_f32x2(h.z));
            s2[3] = add2(s2[3], h2_to_f32x2(h.w));
        }
        float s[8];
        {
            float2 a0 = unpack2(s2[0]), a1 = unpack2(s2[1]);
            float2 a2 = unpack2(s2[2]), a3 = unpack2(s2[3]);
            s[0]=a0.x; s[1]=a0.y; s[2]=a1.x; s[3]=a1.y;
            s[4]=a2.x; s[5]=a2.y; s[6]=a3.x; s[7]=a3.y;
        }
        // reduce across the 16 node-groups within each warp (keep oh bit distinct)
        for (int m = 2; m < 32; m <<= 1)
#pragma unroll
            for (int j = 0; j < 8; ++j)
                s[j] += __shfl_xor_sync(0xffffffffu, s[j], m);
        if (lane < 2)
#pragma unroll
            for (int j = 0; j < 8; ++j)
                red[(lane * 8 + j) * NW3 + wid] = s[j];
    }
    __syncthreads();
    if (tid < 16) {   // lanes 0..15 of warp 0 -> mask 0xffff
        const int o = tid;
        float s = 0.0f;
#pragma unroll
        for (int w = 0; w < NW3; ++w) s += red[o * NW3 + w];
        s *= (1.0f / (float)NN);
        float q = s * s;
        for (int m = 1; m < 16; m <<= 1) q += __shfl_xor_sync(0xffffu, q, m);
        float scale = q / ((1.0f + q) * sqrtf(q));
        outv[o] = scale * s;
    }

    // ---- iterations 1..2: fused agreement + exp + weighted sum ----
    float lg[KPT3];
#pragma unroll
    for (int k = 0; k < KPT3; ++k) lg[k] = 0.0f;

    for (int it = 1; it <= 2; ++it) {
        __syncthreads();
        const ull* ovp = reinterpret_cast<const ull*>(outv) + oh * 4;
        ull ov[4];
#pragma unroll
        for (int j = 0; j < 4; ++j) ov[j] = ovp[j];

        ull sp2[4] = {0ull, 0ull, 0ull, 0ull};
        float se = 0.0f;
#pragma unroll
        for (int k = 0; k < KPT3; ++k) {
            const uint4 h = *reinterpret_cast<const uint4*>(&spri[(g + 128 * k) * 16 + oh * 8]);
            ull p0 = h2_to_f32x2(h.x);
            ull p1 = h2_to_f32x2(h.y);
            ull p2 = h2_to_f32x2(h.z);
            ull p3 = h2_to_f32x2(h.w);
            // agreement half-dot (no max pass — exp safe since ||out||<1 bounds logits)
            ull d2 = fma2(p0, ov[0],
                     fma2(p1, ov[1],
                     fma2(p2, ov[2],
                     fma2(p3, ov[3], 0ull))));
            float2 dd = unpack2(d2);
            float d = dd.x + dd.y;
            d += __shfl_xor_sync(0xffffffffu, d, 1);   // combine the two o-halves
            lg[k] += d;
            float e = __expf(lg[k]);
            se += e;
            ull e2 = pack2(e, e);
            sp2[0] = fma2(e2, p0, sp2[0]);
            sp2[1] = fma2(e2, p1, sp2[1]);
            sp2[2] = fma2(e2, p2, sp2[2]);
            sp2[3] = fma2(e2, p3, sp2[3]);
        }
        float sp[8];
        {
            float2 a0 = unpack2(sp2[0]), a1 = unpack2(sp2[1]);
            float2 a2 = unpack2(sp2[2]), a3 = unpack2(sp2[3]);
            sp[0]=a0.x; sp[1]=a0.y; sp[2]=a1.x; sp[3]=a1.y;
            sp[4]=a2.x; sp[5]=a2.y; sp[6]=a3.x; sp[7]=a3.y;
        }
        // se: full-warp reduce (2x oh redundancy -> exactly 2*true)
        for (int m = 1; m < 32; m <<= 1)
            se += __shfl_xor_sync(0xffffffffu, se, m);
        // sp: reduce across node-groups only (keep oh distinct)
        for (int m = 2; m < 32; m <<= 1)
#pragma unroll
            for (int j = 0; j < 8; ++j)
                sp[j] += __shfl_xor_sync(0xffffffffu, sp[j], m);
        if (lane == 0) sew[wid] = se;
        if (lane < 2)
#pragma unroll
            for (int j = 0; j < 8; ++j)
                red[(lane * 8 + j) * NW3 + wid] = sp[j];
        __syncthreads();

        if (tid < 16) {   // lanes 0..15 of warp 0 -> mask 0xffff
            const int o = tid;
            float sps = 0.0f, ses = 0.0f;
#pragma unroll
            for (int w = 0; w < NW3; ++w) {
                sps += red[o * NW3 + w];
                ses += sew[w];
            }
            float s = sps * (2.0f / ses);   // /2 undoes oh redundancy exactly
            float q = s * s;
            for (int m = 1; m < 16; m <<= 1) q += __shfl_xor_sync(0xffffu, q, m);
            float scale = q / ((1.0f + q) * sqrtf(q));
            float o_ = scale * s;
            outv[o] = o_;
            if (it == 2)
                out[((size_t)cg * BB + b) * DOUT + o] = o_;
        }
    }
}

extern "C" void kernel_launch(void* const* d_in, const int* in_sizes, int n_in,
                              void* d_out, int out_size) {
    const float* x = (const float*)d_in[0];   // [256,1152,8]
    const float* W = (const float*)d_in[1];   // [10,1152,8,16]
    float* out = (float*)d_out;               // [10,256,1,16]

    // 3-launch software pipeline, single stream:
    //   L0: P(0..4)  -> buf0
    //   L1: P(5..9) -> buf1  co-scheduled with  R(0..4) <- buf0   (P CTAs first)
    //   L2: R(5..9) <- buf1
    fused_kernel<<<PBLKS, 256>>>(x, W, out,
        /*c0P=*/0, /*bufP=*/0, /*c0R=*/0, /*bufR=*/0, /*nPblk=*/PBLKS);
    fused_kernel<<<PBLKS + RBLKS, 256>>>(x, W, out,
        /*c0P=*/CH, /*bufP=*/1, /*c0R=*/0, /*bufR=*/0, /*nPblk=*/PBLKS);
    fused_kernel<<<RBLKS, 256>>>(x, W, out,
        /*c0P=*/0, /*bufP=*/0, /*c0R=*/CH, /*bufR=*/1, /*nPblk=*/0);
}

// round 15
// speedup vs baseline: 2.0976x; 2.0976x over previous
#include <cuda_runtime.h>
#include <cuda_fp16.h>
#include <math.h>

#define CC    10
#define CH    5        // capsules per chunk
#define NN    1152
#define DIN   8
#define DOUT  16
#define BB    256

typedef unsigned long long ull;

// Double-buffered fp16 priors scratch: [buf][c_local][b][n][o], 2 x 47.2 MB.
__device__ __half g_pri[2][(size_t)CH * BB * NN * DOUT];

// ---- packed f32x2 helpers (Blackwell FFMA2 — PTX-only) ----
__device__ __forceinline__ ull pack2(float lo, float hi) {
    ull r; asm("mov.b64 %0, {%1, %2};" : "=l"(r) : "f"(lo), "f"(hi)); return r;
}
__device__ __forceinline__ float2 unpack2(ull v) {
    float2 f; asm("mov.b64 {%0, %1}, %2;" : "=f"(f.x), "=f"(f.y) : "l"(v)); return f;
}
__device__ __forceinline__ ull fma2(ull a, ull b, ull c) {
    ull d; asm("fma.rn.f32x2 %0, %1, %2, %3;" : "=l"(d) : "l"(a), "l"(b), "l"(c)); return d;
}
__device__ __forceinline__ ull add2(ull a, ull b) {
    ull d; asm("add.rn.f32x2 %0, %1, %2;" : "=l"(d) : "l"(a), "l"(b)); return d;
}
__device__ __forceinline__ ull h2_to_f32x2(unsigned int h2) {
    ull d;
    asm("{\n\t"
        ".reg .f16 h0, h1;\n\t"
        ".reg .f32 f0, f1;\n\t"
        "mov.b32 {h0, h1}, %1;\n\t"
        "cvt.f32.f16 f0, h0;\n\t"
        "cvt.f32.f16 f1, h1;\n\t"
        "mov.b64 %0, {f0, f1};\n\t"
        "}" : "=l"(d) : "r"(h2));
    return d;
}
__device__ __forceinline__ unsigned int f32x2_to_h2(ull v) {
    unsigned int r;
    asm("{\n\t"
        ".reg .f32 lo, hi;\n\t"
        "mov.b64 {lo, hi}, %1;\n\t"
        "cvt.rn.f16x2.f32 %0, hi, lo;\n\t"
        "}" : "=r"(r) : "l"(v));
    return r;
}

// ================= Kernel 1: priors GEMM (fp32 W) -> g_pri fp16 (R11, + buf) =================
// grid (CH, 9, 8); 256 threads. Thread owns (node n, o-half oh), loops 32 batch elems.
// NO launch-bounds occupancy cap: needs ~96 regs for the resident W slice.
#define ZB 8
#define BPB (BB / ZB)   // 32 batch elems per block

__global__ __launch_bounds__(256)
void priors_kernel(const float* __restrict__ x, const float* __restrict__ W,
                   int c0, int buf) {
    const int tid = threadIdx.x;
    const int oh  = tid & 1;                   // o-half: owns o = oh*8 .. oh*8+7
    const int nn  = tid >> 1;                  // 0..127
    const int cl  = blockIdx.x;                // chunk-local capsule
    const int cg  = c0 + cl;                   // global capsule (for W)
    const int n   = blockIdx.y * 128 + nn;
    const int b0  = blockIdx.z * BPB;

    // Load this (n, oh) W slice ONCE: 8 i x 8 o = 64 floats -> 32 f32x2 regs.
    ull w2[32];
    {
        const float4* wr = reinterpret_cast<const float4*>(
            W + (((size_t)cg * NN + n) * DIN) * DOUT + oh * 8);
#pragma unroll
        for (int i = 0; i < 8; ++i) {
            float4 q0 = wr[i * 4 + 0];
            float4 q1 = wr[i * 4 + 1];
            w2[i * 4 + 0] = pack2(q0.x, q0.y);
            w2[i * 4 + 1] = pack2(q0.z, q0.w);
            w2[i * 4 + 2] = pack2(q1.x, q1.y);
            w2[i * 4 + 3] = pack2(q1.z, q1.w);
        }
    }

    uint4* op = reinterpret_cast<uint4*>(g_pri[buf]);

#pragma unroll 2
    for (int bb = 0; bb < BPB; ++bb) {
        const int b = b0 + bb;
        const float4* xr = reinterpret_cast<const float4*>(x + ((size_t)b * NN + n) * DIN);
        float4 v0 = xr[0], v1 = xr[1];
        float xa[8];
        xa[0]=v0.x; xa[1]=v0.y; xa[2]=v0.z; xa[3]=v0.w;
        xa[4]=v1.x; xa[5]=v1.y; xa[6]=v1.z; xa[7]=v1.w;

        ull acc[4] = {0ull, 0ull, 0ull, 0ull};
#pragma unroll
        for (int i = 0; i < 8; ++i) {
            ull xs = pack2(xa[i], xa[i]);
#pragma unroll
            for (int p = 0; p < 4; ++p)
                acc[p] = fma2(xs, w2[i * 4 + p], acc[p]);
        }
        uint4 o;
        o.x = f32x2_to_h2(acc[0]);
        o.y = f32x2_to_h2(acc[1]);
        o.z = f32x2_to_h2(acc[2]);
        o.w = f32x2_to_h2(acc[3]);
        op[((size_t)(cl * BB + b) * NN + n) * 2 + oh] = o;
    }
}

// ================= Kernel 2: routing, priors tile in SMEM (R11, + buf) =================
// grid (CH, BB); 256 threads (8 warps), 4 CTAs/SM.
#define T3    256
#define NW3   8
#define KPT3  9    // nodes per thread: NN / (T3/2)

__global__ __launch_bounds__(T3, 4)
void routing_kernel(float* __restrict__ out, int c0, int buf) {
    __shared__ __align__(16) __half spri[NN * DOUT];   // 36864 B
    __shared__ float red[16 * NW3];
    __shared__ float sew[NW3];
    __shared__ __align__(16) float outv[16];

    const int tid  = threadIdx.x;
    const int lane = tid & 31;
    const int wid  = tid >> 5;
    const int oh   = tid & 1;     // owns o = oh*8 .. oh*8+7
    const int g    = tid >> 1;    // node group 0..127
    const int cl   = blockIdx.x;  // chunk-local capsule
    const int cg   = c0 + cl;     // global capsule (for out)
    const int b    = blockIdx.y;

    // ---- load priors tile: 2304 x 16B, fully coalesced ----
    {
        const uint4* src = reinterpret_cast<const uint4*>(g_pri[buf])
                         + (size_t)(cl * BB + b) * NN * 2;
        uint4* dst = reinterpret_cast<uint4*>(spri);
#pragma unroll
        for (int t = 0; t < 9; ++t)
            dst[tid + t * T3] = src[tid + t * T3];
    }
    __syncthreads();

    // ---- iter 0: uniform weights -> s = mean over n, squash ----
    {
        ull s2[4] = {0ull, 0ull, 0ull, 0ull};
#pragma unroll
        for (int k = 0; k < KPT3; ++k) {
            const uint4 h = *reinterpret_cast<const uint4*>(&spri[(g + 128 * k) * 16 + oh * 8]);
            s2[0] = add2(s2[0], h2_to_f32x2(h.x));
            s2[1] = add2(s2[1], h2_to_f32x2(h.y));
            s2[2] = add2(s2[2], h2_to_f32x2(h.z));
            s2[3] = add2(s2[3], h2_to_f32x2(h.w));
        }
        float s[8];
        {
            float2 a0 = unpack2(s2[0]), a1 = unpack2(s2[1]);
            float2 a2 = unpack2(s2[2]), a3 = unpack2(s2[3]);
            s[0]=a0.x; s[1]=a0.y; s[2]=a1.x; s[3]=a1.y;
            s[4]=a2.x; s[5]=a2.y; s[6]=a3.x; s[7]=a3.y;
        }
        // reduce across the 16 node-groups within each warp (keep oh bit distinct)
        for (int m = 2; m < 32; m <<= 1)
#pragma unroll
            for (int j = 0; j < 8; ++j)
                s[j] += __shfl_xor_sync(0xffffffffu, s[j], m);
        if (lane < 2)
#pragma unroll
            for (int j = 0; j < 8; ++j)
                red[(lane * 8 + j) * NW3 + wid] = s[j];
    }
    __syncthreads();
    if (tid < 16) {   // lanes 0..15 of warp 0 -> mask 0xffff
        const int o = tid;
        float s = 0.0f;
#pragma unroll
        for (int w = 0; w < NW3; ++w) s += red[o * NW3 + w];
        s *= (1.0f / (float)NN);
        float q = s * s;
        for (int m = 1; m < 16; m <<= 1) q += __shfl_xor_sync(0xffffu, q, m);
        float scale = q / ((1.0f + q) * sqrtf(q));
        outv[o] = scale * s;
    }

    // ---- iterations 1..2: fused agreement + exp + weighted sum ----
    float lg[KPT3];
#pragma unroll
    for (int k = 0; k < KPT3; ++k) lg[k] = 0.0f;

    for (int it = 1; it <= 2; ++it) {
        __syncthreads();
        const ull* ovp = reinterpret_cast<const ull*>(outv) + oh * 4;
        ull ov[4];
#pragma unroll
        for (int j = 0; j < 4; ++j) ov[j] = ovp[j];

        ull sp2[4] = {0ull, 0ull, 0ull, 0ull};
        float se = 0.0f;
#pragma unroll
        for (int k = 0; k < KPT3; ++k) {
            const uint4 h = *reinterpret_cast<const uint4*>(&spri[(g + 128 * k) * 16 + oh * 8]);
            ull p0 = h2_to_f32x2(h.x);
            ull p1 = h2_to_f32x2(h.y);
            ull p2 = h2_to_f32x2(h.z);
            ull p3 = h2_to_f32x2(h.w);
            // agreement half-dot (no max pass — exp safe since ||out||<1 bounds logits)
            ull d2 = fma2(p0, ov[0],
                     fma2(p1, ov[1],
                     fma2(p2, ov[2],
                     fma2(p3, ov[3], 0ull))));
            float2 dd = unpack2(d2);
            float d = dd.x + dd.y;
            d += __shfl_xor_sync(0xffffffffu, d, 1);   // combine the two o-halves
            lg[k] += d;
            float e = __expf(lg[k]);
            se += e;
            ull e2 = pack2(e, e);
            sp2[0] = fma2(e2, p0, sp2[0]);
            sp2[1] = fma2(e2, p1, sp2[1]);
            sp2[2] = fma2(e2, p2, sp2[2]);
            sp2[3] = fma2(e2, p3, sp2[3]);
        }
        float sp[8];
        {
            float2 a0 = unpack2(sp2[0]), a1 = unpack2(sp2[1]);
            float2 a2 = unpack2(sp2[2]), a3 = unpack2(sp2[3]);
            sp[0]=a0.x; sp[1]=a0.y; sp[2]=a1.x; sp[3]=a1.y;
            sp[4]=a2.x; sp[5]=a2.y; sp[6]=a3.x; sp[7]=a3.y;
        }
        // se: full-warp reduce (2x oh redundancy -> exactly 2*true)
        for (int m = 1; m < 32; m <<= 1)
            se += __shfl_xor_sync(0xffffffffu, se, m);
        // sp: reduce across node-groups only (keep oh distinct)
        for (int m = 2; m < 32; m <<= 1)
#pragma unroll
            for (int j = 0; j < 8; ++j)
                sp[j] += __shfl_xor_sync(0xffffffffu, sp[j], m);
        if (lane == 0) sew[wid] = se;
        if (lane < 2)
#pragma unroll
            for (int j = 0; j < 8; ++j)
                red[(lane * 8 + j) * NW3 + wid] = sp[j];
        __syncthreads();

        if (tid < 16) {   // lanes 0..15 of warp 0 -> mask 0xffff
            const int o = tid;
            float sps = 0.0f, ses = 0.0f;
#pragma unroll
            for (int w = 0; w < NW3; ++w) {
                sps += red[o * NW3 + w];
                ses += sew[w];
            }
            float s = sps * (2.0f / ses);   // /2 undoes oh redundancy exactly
            float q = s * s;
            for (int m = 1; m < 16; m <<= 1) q += __shfl_xor_sync(0xffffu, q, m);
            float scale = q / ((1.0f + q) * sqrtf(q));
            float o_ = scale * s;
            outv[o] = o_;
            if (it == 2)
                out[((size_t)cg * BB + b) * DOUT + o] = o_;
        }
    }
}

extern "C" void kernel_launch(void* const* d_in, const int* in_sizes, int n_in,
                              void* d_out, int out_size) {
    const float* x = (const float*)d_in[0];   // [256,1152,8]
    const float* W = (const float*)d_in[1];   // [10,1152,8,16]
    float* out = (float*)d_out;               // [10,256,1,16]

    dim3 gp(CH, NN / 128, ZB);                // (5, 9, 8)
    dim3 gr(CH, BB);                          // (5, 256)

    // Fork/join pipeline (graph-capturable: kernels + events only, no allocs):
    //   main:  P1(buf0) ─e1─┬─ R1(buf0) ──────┬─ R2(buf1)
    //   side:               └─ P2(buf1) ──e2──┘
    // P2 runs CONCURRENTLY with R1 (disjoint buffers). Streams/events are
    // host objects, created per call (kernel_launch runs ≤3 times, never on replay).
    cudaStream_t s2;
    cudaStreamCreateWithFlags(&s2, cudaStreamNonBlocking);
    cudaEvent_t e1, e2;
    cudaEventCreateWithFlags(&e1, cudaEventDisableTiming);
    cudaEventCreateWithFlags(&e2, cudaEventDisableTiming);

    priors_kernel<<<gp, 256>>>(x, W, 0, 0);          // P1 -> buf0   (main stream)
    cudaEventRecord(e1, 0);
    cudaStreamWaitEvent(s2, e1, 0);                   // fork
    priors_kernel<<<gp, 256, 0, s2>>>(x, W, CH, 1);  // P2 -> buf1   (side stream)
    routing_kernel<<<gr, T3>>>(out, 0, 0);            // R1 <- buf0   (main stream)
    cudaEventRecord(e2, s2);
    cudaStreamWaitEvent(0, e2, 0);                    // join
    routing_kernel<<<gr, T3>>>(out, CH, 1);           // R2 <- buf1   (main stream)
}

// round 16
// speedup vs baseline: 2.3437x; 1.1173x over previous
#include <cuda_runtime.h>
#include <cuda_fp16.h>
#include <math.h>

#define CC    10
#define CH    5        // capsules per chunk
#define NN    1152
#define DIN   8
#define DOUT  16
#define BB    256

typedef unsigned long long ull;

// fp16 priors scratch for ONE 5-capsule chunk (47.2 MB), reused in place.
__device__ __half g_pri[(size_t)CH * BB * NN * DOUT];

// ---- packed f32x2 helpers (Blackwell FFMA2 — PTX-only) ----
__device__ __forceinline__ ull pack2(float lo, float hi) {
    ull r; asm("mov.b64 %0, {%1, %2};" : "=l"(r) : "f"(lo), "f"(hi)); return r;
}
__device__ __forceinline__ float2 unpack2(ull v) {
    float2 f; asm("mov.b64 {%0, %1}, %2;" : "=f"(f.x), "=f"(f.y) : "l"(v)); return f;
}
__device__ __forceinline__ ull fma2(ull a, ull b, ull c) {
    ull d; asm("fma.rn.f32x2 %0, %1, %2, %3;" : "=l"(d) : "l"(a), "l"(b), "l"(c)); return d;
}
__device__ __forceinline__ ull add2(ull a, ull b) {
    ull d; asm("add.rn.f32x2 %0, %1, %2;" : "=l"(d) : "l"(a), "l"(b)); return d;
}
__device__ __forceinline__ ull h2_to_f32x2(unsigned int h2) {
    ull d;
    asm("{\n\t"
        ".reg .f16 h0, h1;\n\t"
        ".reg .f32 f0, f1;\n\t"
        "mov.b32 {h0, h1}, %1;\n\t"
        "cvt.f32.f16 f0, h0;\n\t"
        "cvt.f32.f16 f1, h1;\n\t"
        "mov.b64 %0, {f0, f1};\n\t"
        "}" : "=l"(d) : "r"(h2));
    return d;
}
__device__ __forceinline__ unsigned int f32x2_to_h2(ull v) {
    unsigned int r;
    asm("{\n\t"
        ".reg .f32 lo, hi;\n\t"
        "mov.b64 {lo, hi}, %1;\n\t"
        "cvt.rn.f16x2.f32 %0, hi, lo;\n\t"
        "}" : "=r"(r) : "l"(v));
    return r;
}

// ================= Kernel 1: priors GEMM (fp32 W) -> g_pri fp16 (R11 verbatim) ==========
// grid (CH, 9, 8); 256 threads. Thread owns (node n, o-half oh), loops 32 batch elems.
#define ZB 8
#define BPB (BB / ZB)   // 32 batch elems per block

__global__ __launch_bounds__(256)
void priors_kernel(const float* __restrict__ x, const float* __restrict__ W, int c0) {
    const int tid = threadIdx.x;
    const int oh  = tid & 1;                   // o-half: owns o = oh*8 .. oh*8+7
    const int nn  = tid >> 1;                  // 0..127
    const int cl  = blockIdx.x;                // chunk-local capsule
    const int cg  = c0 + cl;                   // global capsule (for W)
    const int n   = blockIdx.y * 128 + nn;
    const int b0  = blockIdx.z * BPB;

    // Load this (n, oh) W slice ONCE: 8 i x 8 o = 64 floats -> 32 f32x2 regs.
    ull w2[32];
    {
        const float4* wr = reinterpret_cast<const float4*>(
            W + (((size_t)cg * NN + n) * DIN) * DOUT + oh * 8);
#pragma unroll
        for (int i = 0; i < 8; ++i) {
            float4 q0 = wr[i * 4 + 0];
            float4 q1 = wr[i * 4 + 1];
            w2[i * 4 + 0] = pack2(q0.x, q0.y);
            w2[i * 4 + 1] = pack2(q0.z, q0.w);
            w2[i * 4 + 2] = pack2(q1.x, q1.y);
            w2[i * 4 + 3] = pack2(q1.z, q1.w);
        }
    }

    uint4* op = reinterpret_cast<uint4*>(g_pri);

#pragma unroll 2
    for (int bb = 0; bb < BPB; ++bb) {
        const int b = b0 + bb;
        const float4* xr = reinterpret_cast<const float4*>(x + ((size_t)b * NN + n) * DIN);
        float4 v0 = xr[0], v1 = xr[1];
        float xa[8];
        xa[0]=v0.x; xa[1]=v0.y; xa[2]=v0.z; xa[3]=v0.w;
        xa[4]=v1.x; xa[5]=v1.y; xa[6]=v1.z; xa[7]=v1.w;

        ull acc[4] = {0ull, 0ull, 0ull, 0ull};
#pragma unroll
        for (int i = 0; i < 8; ++i) {
            ull xs = pack2(xa[i], xa[i]);
#pragma unroll
            for (int p = 0; p < 4; ++p)
                acc[p] = fma2(xs, w2[i * 4 + p], acc[p]);
        }
        uint4 o;
        o.x = f32x2_to_h2(acc[0]);
        o.y = f32x2_to_h2(acc[1]);
        o.z = f32x2_to_h2(acc[2]);
        o.w = f32x2_to_h2(acc[3]);
        op[((size_t)(cl * BB + b) * NN + n) * 2 + oh] = o;
    }
}

// ================= Kernel 2: routing, iter-0 FUSED into tile load =================
// grid (CH, BB); 256 threads (8 warps), 4 CTAs/SM.
// KEY: thread tid's scan elements are uint4 indices tid+256k — exactly what it
// loads. So the iter-0 sum is computed from the load registers directly; the
// smem tile is only needed for iterations 1-2.
#define T3    256
#define NW3   8
#define KPT3  9    // nodes per thread: NN / (T3/2)

__global__ __launch_bounds__(T3, 4)
void routing_kernel(float* __restrict__ out, int c0) {
    __shared__ __align__(16) __half spri[NN * DOUT];   // 36864 B
    __shared__ float red[16 * NW3];
    __shared__ float sew[NW3];
    __shared__ __align__(16) float outv[16];

    const int tid  = threadIdx.x;
    const int lane = tid & 31;
    const int wid  = tid >> 5;
    const int oh   = tid & 1;     // owns o = oh*8 .. oh*8+7
    const int g    = tid >> 1;    // node group 0..127
    const int cl   = blockIdx.x;  // chunk-local capsule
    const int cg   = c0 + cl;     // global capsule (for out)
    const int b    = blockIdx.y;

    // ---- FUSED: load priors tile (coalesced) + iter-0 sum from load registers ----
    {
        const uint4* src = reinterpret_cast<const uint4*>(g_pri) + (size_t)(cl * BB + b) * NN * 2;
        uint4* dst = reinterpret_cast<uint4*>(spri);
        ull s2[4] = {0ull, 0ull, 0ull, 0ull};
#pragma unroll
        for (int t = 0; t < KPT3; ++t) {
            uint4 h = src[tid + t * T3];
            dst[tid + t * T3] = h;
            s2[0] = add2(s2[0], h2_to_f32x2(h.x));
            s2[1] = add2(s2[1], h2_to_f32x2(h.y));
            s2[2] = add2(s2[2], h2_to_f32x2(h.z));
            s2[3] = add2(s2[3], h2_to_f32x2(h.w));
        }
        float s[8];
        {
            float2 a0 = unpack2(s2[0]), a1 = unpack2(s2[1]);
            float2 a2 = unpack2(s2[2]), a3 = unpack2(s2[3]);
            s[0]=a0.x; s[1]=a0.y; s[2]=a1.x; s[3]=a1.y;
            s[4]=a2.x; s[5]=a2.y; s[6]=a3.x; s[7]=a3.y;
        }
        // reduce across the 16 node-groups within each warp (keep oh bit distinct)
        for (int m = 2; m < 32; m <<= 1)
#pragma unroll
            for (int j = 0; j < 8; ++j)
                s[j] += __shfl_xor_sync(0xffffffffu, s[j], m);
        if (lane < 2)
#pragma unroll
            for (int j = 0; j < 8; ++j)
                red[(lane * 8 + j) * NW3 + wid] = s[j];
    }
    __syncthreads();   // covers: tile visible for iters 1-2, red visible below

    // iter-0 finalize: s = mean over n, squash
    if (tid < 16) {   // lanes 0..15 of warp 0 -> mask 0xffff
        const int o = tid;
        float s = 0.0f;
#pragma unroll
        for (int w = 0; w < NW3; ++w) s += red[o * NW3 + w];
        s *= (1.0f / (float)NN);
        float q = s * s;
        for (int m = 1; m < 16; m <<= 1) q += __shfl_xor_sync(0xffffu, q, m);
        float scale = q / ((1.0f + q) * sqrtf(q));
        outv[o] = scale * s;
    }

    // ---- iterations 1..2: fused agreement + exp + weighted sum ----
    float lg[KPT3];
#pragma unroll
    for (int k = 0; k < KPT3; ++k) lg[k] = 0.0f;

    for (int it = 1; it <= 2; ++it) {
        __syncthreads();
        const ull* ovp = reinterpret_cast<const ull*>(outv) + oh * 4;
        ull ov[4];
#pragma unroll
        for (int j = 0; j < 4; ++j) ov[j] = ovp[j];

        ull sp2[4] = {0ull, 0ull, 0ull, 0ull};
        float se = 0.0f;
#pragma unroll
        for (int k = 0; k < KPT3; ++k) {
            const uint4 h = *reinterpret_cast<const uint4*>(&spri[(g + 128 * k) * 16 + oh * 8]);
            ull p0 = h2_to_f32x2(h.x);
            ull p1 = h2_to_f32x2(h.y);
            ull p2 = h2_to_f32x2(h.z);
            ull p3 = h2_to_f32x2(h.w);
            // agreement half-dot (no max pass — exp safe since ||out||<1 bounds logits)
            ull d2 = fma2(p0, ov[0],
                     fma2(p1, ov[1],
                     fma2(p2, ov[2],
                     fma2(p3, ov[3], 0ull))));
            float2 dd = unpack2(d2);
            float d = dd.x + dd.y;
            d += __shfl_xor_sync(0xffffffffu, d, 1);   // combine the two o-halves
            lg[k] += d;
            float e = __expf(lg[k]);
            se += e;
            ull e2 = pack2(e, e);
            sp2[0] = fma2(e2, p0, sp2[0]);
            sp2[1] = fma2(e2, p1, sp2[1]);
            sp2[2] = fma2(e2, p2, sp2[2]);
            sp2[3] = fma2(e2, p3, sp2[3]);
        }
        float sp[8];
        {
            float2 a0 = unpack2(sp2[0]), a1 = unpack2(sp2[1]);
            float2 a2 = unpack2(sp2[2]), a3 = unpack2(sp2[3]);
            sp[0]=a0.x; sp[1]=a0.y; sp[2]=a1.x; sp[3]=a1.y;
            sp[4]=a2.x; sp[5]=a2.y; sp[6]=a3.x; sp[7]=a3.y;
        }
        // se: full-warp reduce (2x oh redundancy -> exactly 2*true)
        for (int m = 1; m < 32; m <<= 1)
            se += __shfl_xor_sync(0xffffffffu, se, m);
        // sp: reduce across node-groups only (keep oh distinct)
        for (int m = 2; m < 32; m <<= 1)
#pragma unroll
            for (int j = 0; j < 8; ++j)
                sp[j] += __shfl_xor_sync(0xffffffffu, sp[j], m);
        if (lane == 0) sew[wid] = se;
        if (lane < 2)
#pragma unroll
            for (int j = 0; j < 8; ++j)
                red[(lane * 8 + j) * NW3 + wid] = sp[j];
        __syncthreads();

        if (tid < 16) {   // lanes 0..15 of warp 0 -> mask 0xffff
            const int o = tid;
            float sps = 0.0f, ses = 0.0f;
#pragma unroll
            for (int w = 0; w < NW3; ++w) {
                sps += red[o * NW3 + w];
                ses += sew[w];
            }
            float s = sps * (2.0f / ses);   // /2 undoes oh redundancy exactly
            float q = s * s;
            for (int m = 1; m < 16; m <<= 1) q += __shfl_xor_sync(0xffffu, q, m);
            float scale = q / ((1.0f + q) * sqrtf(q));
            float o_ = scale * s;
            outv[o] = o_;
            if (it == 2)
                out[((size_t)cg * BB + b) * DOUT + o] = o_;
        }
    }
}

extern "C" void kernel_launch(void* const* d_in, const int* in_sizes, int n_in,
                              void* d_out, int out_size) {
    const float* x = (const float*)d_in[0];   // [256,1152,8]
    const float* W = (const float*)d_in[1];   // [10,1152,8,16]
    float* out = (float*)d_out;               // [10,256,1,16]

    dim3 gp(CH, NN / 128, ZB);                // (5, 9, 8)
    dim3 gr(CH, BB);                          // (5, 256)

    // R11 chunked pipeline (best known structure).
    priors_kernel<<<gp, 256>>>(x, W, 0);
    routing_kernel<<<gr, T3>>>(out, 0);
    priors_kernel<<<gp, 256>>>(x, W, CH);
    routing_kernel<<<gr, T3>>>(out, CH);
}